// round 1
// baseline (speedup 1.0000x reference)
#include <cuda_runtime.h>

#define NNODE 50000
#define NEDGE 300000
#define HDIM  128
#define GTAB  1024
#define EPSBN 1e-5f

// ---------------- scratch (device globals; no allocation) ----------------
__device__ float g_a1[(size_t)NEDGE * HDIM];   // lrelu(pre1), raw (pre-BN)
__device__ float g_a2[(size_t)NEDGE * HDIM];   // lrelu(pre2), raw
__device__ float g_xd[(size_t)NNODE * HDIM];   // x@Wd + bd
__device__ float g_z [(size_t)NNODE * HDIM];   // v*xd + scatter(m_st)
__device__ float g_an[(size_t)NNODE * HDIM];   // lrelu(z@Wn1+bn1), raw
__device__ float g_tab[4 * GTAB * HDIM];       // composed gaussian tables
__device__ float g_WbWe1[200 * HDIM];          // Wb @ We1[128:256]
__device__ float g_cvec[HDIM];                 // be1 + bb @ We1[128:256]
__device__ float g_W2p[HDIM * HDIM];  __device__ float g_b2p[HDIM];
__device__ float g_W3p[HDIM * HDIM];  __device__ float g_b3p[HDIM];
__device__ float g_Wn2p[HDIM * HDIM]; __device__ float g_bn2p[HDIM];
__device__ float g_sums[6][HDIM];              // [0,1]=bn1 sum/sq, [2,3]=bn2, [4,5]=bnN

// ---------------- tiny prep kernels ----------------
__global__ void zero_stats() {
    ((float*)g_sums)[threadIdx.x] = 0.0f;
}

// g_WbWe1[r][n] = sum_k Wb[r][k] * We1[128+k][n]
__global__ void wbwe1_kernel(const float* __restrict__ Wb,
                             const float* __restrict__ We1) {
    int r = blockIdx.x, n = threadIdx.x;
    float acc = 0.f;
    #pragma unroll 8
    for (int k = 0; k < 128; k++)
        acc += Wb[r * 128 + k] * We1[(128 + k) * 128 + n];
    g_WbWe1[r * 128 + n] = acc;
}

// g_cvec[n] = be1[n] + sum_k bb[k] * We1[128+k][n]
__global__ void cvec_kernel(const float* __restrict__ bb,
                            const float* __restrict__ We1,
                            const float* __restrict__ be1) {
    int n = threadIdx.x;
    float acc = be1[n];
    #pragma unroll 8
    for (int k = 0; k < 128; k++)
        acc += bb[k] * We1[(128 + k) * 128 + n];
    g_cvec[n] = acc;
}

// g_tab[(c*GTAB+g)][n] = sum_j exp(-(u_g - ctr_j)^2 * K^2/2) * g_WbWe1[c*50+j][n]
__global__ void table_kernel() {
    __shared__ float gs[64];
    int b = blockIdx.x;
    int c = b >> 10;            // GTAB = 1024
    int gi = b & (GTAB - 1);
    float u = (float)gi * (1.0f / (GTAB - 1));
    int tid = threadIdx.x;
    if (tid < 50) {
        float d = u - (float)tid * (1.0f / 49.0f);
        gs[tid] = __expf(-d * d * 1250.0f);   // 1/(2*(1/50)^2) = 1250
    }
    __syncthreads();
    float acc = 0.f;
    #pragma unroll
    for (int j = 0; j < 50; j++)
        acc += gs[j] * g_WbWe1[(c * 50 + j) * 128 + tid];
    g_tab[b * 128 + tid] = acc;
}

// Fold BN (stats at sidx) into next GEMM: Wdst = diag(s) Wsrc, bdst = t@Wsrc + be
__global__ void fold_kernel(int sidx, float invM,
                            const float* __restrict__ gamma,
                            const float* __restrict__ beta,
                            const float* __restrict__ Wsrc,
                            const float* __restrict__ be) {
    float* Wdst = (sidx == 0) ? g_W2p : (sidx == 2) ? g_W3p : g_Wn2p;
    float* bdst = (sidx == 0) ? g_b2p : (sidx == 2) ? g_b3p : g_bn2p;
    int n = threadIdx.x;
    if (blockIdx.x < 128) {
        int k = blockIdx.x;
        float m = g_sums[sidx][k] * invM;
        float var = g_sums[sidx + 1][k] * invM - m * m;
        float s = gamma[k] * rsqrtf(var + EPSBN);
        Wdst[k * 128 + n] = s * Wsrc[k * 128 + n];
    } else {
        float acc = be[n];
        for (int k = 0; k < 128; k++) {
            float m = g_sums[sidx][k] * invM;
            float var = g_sums[sidx + 1][k] * invM - m * m;
            float s = gamma[k] * rsqrtf(var + EPSBN);
            float t = beta[k] - m * s;
            acc += t * Wsrc[k * 128 + n];
        }
        bdst[n] = acc;
    }
}

// ---------------- main tiled GEMM (128x128 tile, 256 threads, 8x8/thread) ----------------
enum { M_XD = 0, M_E1 = 1, M_E2 = 2, M_E3 = 3, M_N1 = 4, M_OUT = 5 };

template <int MODE>
__global__ __launch_bounds__(256)
void gemm_kernel(const float* __restrict__ A, const float* __restrict__ Wparam,
                 const float* __restrict__ biasExt,
                 const float* __restrict__ x, const float* __restrict__ ea,
                 const int* __restrict__ eidx, const float* __restrict__ vparam,
                 float* __restrict__ outp, int M) {
    constexpr int KDIM = (MODE == M_E1) ? 256 : 128;
    __shared__ float As[16][132];
    __shared__ float Ws[16][132];

    const int tid = threadIdx.x;
    const int blockRow = blockIdx.x * 128;
    const int tr = tid >> 4;
    const int tc = tid & 15;
    const int c0 = tc * 8;

    const float* W = (MODE == M_E2) ? g_W2p
                   : (MODE == M_E3) ? g_W3p
                   : (MODE == M_OUT) ? g_Wn2p : Wparam;
    const float* bias = (MODE == M_E1) ? g_cvec
                      : (MODE == M_E2) ? g_b2p
                      : (MODE == M_E3) ? g_b3p
                      : (MODE == M_OUT) ? g_bn2p : biasExt;
    const float* Aeff = (MODE == M_E2) ? g_a1
                      : (MODE == M_E3) ? g_a2
                      : (MODE == M_N1) ? g_z
                      : (MODE == M_OUT) ? g_an : A;

    // loader roles: 2 threads per row, 8 floats each
    const int lr = tid >> 1;
    const int lh = (tid & 1) * 8;
    int gsrc = 0, gdst = 0;
    const float* arow = nullptr;
    {
        int r = blockRow + lr;
        if (r > M - 1) r = M - 1;
        if (MODE == M_E1) { gsrc = eidx[r]; gdst = eidx[NEDGE + r]; }
        else              { arow = Aeff + (size_t)r * 128; }
    }

    float acc[8][8];
    #pragma unroll
    for (int i = 0; i < 8; i++)
        #pragma unroll
        for (int j = 0; j < 8; j++) acc[i][j] = 0.f;

    #pragma unroll 1
    for (int k0 = 0; k0 < KDIM; k0 += 16) {
        const float* ap;
        if (MODE == M_E1)
            ap = x + (size_t)((k0 < 128) ? gsrc : gdst) * 128 + (k0 & 127) + lh;
        else
            ap = arow + k0 + lh;
        float4 a0 = *(const float4*)ap;
        float4 a1 = *(const float4*)(ap + 4);

        int krow = k0 + tr;
        if (MODE == M_E1 && krow >= 128) krow += 128;   // skip gt rows (folded into table)
        float4 b0 = *(const float4*)(W + (size_t)krow * 128 + c0);
        float4 b1 = *(const float4*)(W + (size_t)krow * 128 + c0 + 4);

        __syncthreads();
        As[lh + 0][lr] = a0.x; As[lh + 1][lr] = a0.y;
        As[lh + 2][lr] = a0.z; As[lh + 3][lr] = a0.w;
        As[lh + 4][lr] = a1.x; As[lh + 5][lr] = a1.y;
        As[lh + 6][lr] = a1.z; As[lh + 7][lr] = a1.w;
        *(float4*)&Ws[tr][c0]     = b0;
        *(float4*)&Ws[tr][c0 + 4] = b1;
        __syncthreads();

        #pragma unroll
        for (int kk = 0; kk < 16; kk++) {
            float af[8], bf[8];
            *(float4*)(af)     = *(const float4*)&As[kk][tr * 8];
            *(float4*)(af + 4) = *(const float4*)&As[kk][tr * 8 + 4];
            *(float4*)(bf)     = *(const float4*)&Ws[kk][c0];
            *(float4*)(bf + 4) = *(const float4*)&Ws[kk][c0 + 4];
            #pragma unroll
            for (int i = 0; i < 8; i++)
                #pragma unroll
                for (int j = 0; j < 8; j++)
                    acc[i][j] += af[i] * bf[j];
        }
    }
    __syncthreads();   // smem free for epilogue reductions

    float bj[8];
    #pragma unroll
    for (int j = 0; j < 8; j++) bj[j] = bias[c0 + j];

    // ------------- epilogues -------------
    if (MODE == M_XD) {
        float vj[8];
        #pragma unroll
        for (int j = 0; j < 8; j++) vj[j] = vparam[c0 + j];
        #pragma unroll
        for (int i = 0; i < 8; i++) {
            int r = blockRow + tr * 8 + i;
            if (r >= M) break;
            float vals[8], zv[8];
            #pragma unroll
            for (int j = 0; j < 8; j++) { vals[j] = acc[i][j] + bj[j]; zv[j] = vj[j] * vals[j]; }
            float* dp = g_xd + (size_t)r * 128 + c0;
            *(float4*)dp       = make_float4(vals[0], vals[1], vals[2], vals[3]);
            *(float4*)(dp + 4) = make_float4(vals[4], vals[5], vals[6], vals[7]);
            float* zp = g_z + (size_t)r * 128 + c0;
            *(float4*)zp       = make_float4(zv[0], zv[1], zv[2], zv[3]);
            *(float4*)(zp + 4) = make_float4(zv[4], zv[5], zv[6], zv[7]);
        }
        return;
    }

    if (MODE == M_E3) {
        #pragma unroll 1
        for (int i = 0; i < 8; i++) {
            int r = blockRow + tr * 8 + i;
            if (r >= M) break;
            int s_ = eidx[r], d_ = eidx[NEDGE + r];
            float coeff = cosf(1.5707963267948966f * ea[(size_t)r * 4 + 3]);
            const float* xp = g_xd + (size_t)s_ * 128 + c0;
            float4 x0 = *(const float4*)xp;
            float4 x1 = *(const float4*)(xp + 4);
            float xv[8] = {x0.x, x0.y, x0.z, x0.w, x1.x, x1.y, x1.z, x1.w};
            float* zp = g_z + (size_t)d_ * 128 + c0;
            #pragma unroll
            for (int j = 0; j < 8; j++)
                atomicAdd(zp + j, coeff * (acc[i][j] + bj[j]) * xv[j]);
        }
        return;
    }

    if (MODE == M_OUT) {
        #pragma unroll
        for (int i = 0; i < 8; i++) {
            int r = blockRow + tr * 8 + i;
            if (r >= M) break;
            const float* xp = x + (size_t)r * 128 + c0;
            float4 x0 = *(const float4*)xp;
            float4 x1 = *(const float4*)(xp + 4);
            float vals[8];
            vals[0] = acc[i][0] + bj[0] + x0.x; vals[1] = acc[i][1] + bj[1] + x0.y;
            vals[2] = acc[i][2] + bj[2] + x0.z; vals[3] = acc[i][3] + bj[3] + x0.w;
            vals[4] = acc[i][4] + bj[4] + x1.x; vals[5] = acc[i][5] + bj[5] + x1.y;
            vals[6] = acc[i][6] + bj[6] + x1.z; vals[7] = acc[i][7] + bj[7] + x1.w;
            float* dp = outp + (size_t)r * 128 + c0;
            *(float4*)dp       = make_float4(vals[0], vals[1], vals[2], vals[3]);
            *(float4*)(dp + 4) = make_float4(vals[4], vals[5], vals[6], vals[7]);
        }
        return;
    }

    // M_E1 / M_E2 / M_N1: lrelu + store raw + batch stats
    {
        constexpr int SIDX = (MODE == M_E1) ? 0 : (MODE == M_E2) ? 2 : 4;
        float* dst = (MODE == M_E1) ? g_a1 : (MODE == M_E2) ? g_a2 : g_an;
        float csum[8], csq[8];
        #pragma unroll
        for (int j = 0; j < 8; j++) { csum[j] = 0.f; csq[j] = 0.f; }

        #pragma unroll 1
        for (int i = 0; i < 8; i++) {
            int r = blockRow + tr * 8 + i;
            if (r >= M) break;
            float vals[8];
            #pragma unroll
            for (int j = 0; j < 8; j++) vals[j] = acc[i][j] + bj[j];

            if (MODE == M_E1) {
                const float* eaR = ea + (size_t)r * 4;
                #pragma unroll
                for (int c = 0; c < 4; c++) {
                    float f = eaR[c];
                    float p = f * (float)(GTAB - 1);
                    int i0 = (int)p;
                    if (i0 < 0) i0 = 0;
                    if (i0 > GTAB - 2) i0 = GTAB - 2;
                    float w = p - (float)i0;
                    const float* t0 = g_tab + ((size_t)(c * GTAB + i0) * 128 + c0);
                    float4 u0 = *(const float4*)t0;
                    float4 u1 = *(const float4*)(t0 + 4);
                    float4 v0 = *(const float4*)(t0 + 128);
                    float4 v1 = *(const float4*)(t0 + 132);
                    vals[0] += u0.x + w * (v0.x - u0.x);
                    vals[1] += u0.y + w * (v0.y - u0.y);
                    vals[2] += u0.z + w * (v0.z - u0.z);
                    vals[3] += u0.w + w * (v0.w - u0.w);
                    vals[4] += u1.x + w * (v1.x - u1.x);
                    vals[5] += u1.y + w * (v1.y - u1.y);
                    vals[6] += u1.z + w * (v1.z - u1.z);
                    vals[7] += u1.w + w * (v1.w - u1.w);
                }
            }

            #pragma unroll
            for (int j = 0; j < 8; j++) {
                float v_ = vals[j];
                v_ = (v_ >= 0.f) ? v_ : 0.01f * v_;
                vals[j] = v_;
                csum[j] += v_;
                csq[j]  += v_ * v_;
            }
            float* dp = dst + (size_t)r * 128 + c0;
            *(float4*)dp       = make_float4(vals[0], vals[1], vals[2], vals[3]);
            *(float4*)(dp + 4) = make_float4(vals[4], vals[5], vals[6], vals[7]);
        }

        // block-level column reduction, then one atomic per column
        #pragma unroll
        for (int j = 0; j < 8; j++) As[tr][c0 + j] = csum[j];
        __syncthreads();
        if (tid < 128) {
            float s = 0.f;
            #pragma unroll
            for (int t = 0; t < 16; t++) s += As[t][tid];
            atomicAdd(&g_sums[SIDX][tid], s);
        }
        __syncthreads();
        #pragma unroll
        for (int j = 0; j < 8; j++) As[tr][c0 + j] = csq[j];
        __syncthreads();
        if (tid < 128) {
            float s = 0.f;
            #pragma unroll
            for (int t = 0; t < 16; t++) s += As[t][tid];
            atomicAdd(&g_sums[SIDX + 1][tid], s);
        }
    }
}

// ---------------- launcher ----------------
extern "C" void kernel_launch(void* const* d_in, const int* in_sizes, int n_in,
                              void* d_out, int out_size) {
    const float* x    = (const float*)d_in[0];
    const float* ea   = (const float*)d_in[1];
    const int*   eidx = (const int*)  d_in[2];
    const float* Wb   = (const float*)d_in[3];
    const float* bb   = (const float*)d_in[4];
    const float* We1  = (const float*)d_in[5];
    const float* be1  = (const float*)d_in[6];
    const float* ge1  = (const float*)d_in[7];
    const float* bte1 = (const float*)d_in[8];
    const float* We2  = (const float*)d_in[9];
    const float* be2  = (const float*)d_in[10];
    const float* ge2  = (const float*)d_in[11];
    const float* bte2 = (const float*)d_in[12];
    const float* We3  = (const float*)d_in[13];
    const float* be3  = (const float*)d_in[14];
    const float* Wd   = (const float*)d_in[15];
    const float* bd   = (const float*)d_in[16];
    const float* v    = (const float*)d_in[17];
    const float* Wn1  = (const float*)d_in[18];
    const float* bn1  = (const float*)d_in[19];
    const float* gn   = (const float*)d_in[20];
    const float* btn  = (const float*)d_in[21];
    const float* Wn2  = (const float*)d_in[22];
    const float* bn2  = (const float*)d_in[23];
    float* outp = (float*)d_out;

    const int gridE = (NEDGE + 127) / 128;   // 2344
    const int gridN = (NNODE + 127) / 128;   // 391

    zero_stats<<<1, 768>>>();
    wbwe1_kernel<<<200, 128>>>(Wb, We1);
    cvec_kernel<<<1, 128>>>(bb, We1, be1);
    table_kernel<<<4 * GTAB, 128>>>();

    // xd = x@Wd + bd ; z = v * xd
    gemm_kernel<M_XD><<<gridN, 256>>>(x, Wd, bd, nullptr, nullptr, nullptr, v, nullptr, NNODE);

    // a1 = lrelu(x[src]@We1_top + x[dst]@We1_bot + table(ea) + cvec), stats -> [0,1]
    gemm_kernel<M_E1><<<gridE, 256>>>(nullptr, We1, nullptr, x, ea, eidx, nullptr, nullptr, NEDGE);
    fold_kernel<<<129, 128>>>(0, 1.0f / NEDGE, ge1, bte1, We2, be2);

    // a2 = lrelu(a1@W2p + b2p), stats -> [2,3]
    gemm_kernel<M_E2><<<gridE, 256>>>(nullptr, nullptr, nullptr, nullptr, nullptr, nullptr, nullptr, nullptr, NEDGE);
    fold_kernel<<<129, 128>>>(2, 1.0f / NEDGE, ge2, bte2, We3, be3);

    // scatter: z[dst] += cos(pi/2*ea3) * (a2@W3p + b3p) * xd[src]
    gemm_kernel<M_E3><<<gridE, 256>>>(nullptr, nullptr, nullptr, nullptr, ea, eidx, nullptr, nullptr, NEDGE);

    // an = lrelu(z@Wn1 + bn1), stats -> [4,5]
    gemm_kernel<M_N1><<<gridN, 256>>>(nullptr, Wn1, bn1, nullptr, nullptr, nullptr, nullptr, nullptr, NNODE);
    fold_kernel<<<129, 128>>>(4, 1.0f / NNODE, gn, btn, Wn2, bn2);

    // out = an@Wn2p + bn2p + x
    gemm_kernel<M_OUT><<<gridN, 256>>>(nullptr, nullptr, nullptr, x, nullptr, nullptr, nullptr, outp, NNODE);
}

// round 2
// speedup vs baseline: 1.4302x; 1.4302x over previous
#include <cuda_runtime.h>

#define NNODE 50000
#define NEDGE 300000
#define HDIM  128
#define GTAB  1024
#define EPSBN 1e-5f
#define EPB   128

// ---------------- scratch (device globals; no allocation) ----------------
__device__ float g_a1[(size_t)NEDGE * HDIM];   // lrelu(pre1), raw (pre-BN)
__device__ float g_a2[(size_t)NEDGE * HDIM];   // lrelu(pre2), raw
__device__ float g_xd[(size_t)NNODE * HDIM];   // x@Wd + bd
__device__ float g_z [(size_t)NNODE * HDIM];   // v*xd + scatter(m_st)
__device__ float g_an[(size_t)NNODE * HDIM];   // lrelu(z@Wn1+bn1), raw
__device__ float g_xtop[(size_t)NNODE * HDIM]; // x @ We1[0:128]
__device__ float g_xbot[(size_t)NNODE * HDIM]; // x @ We1[256:384]
__device__ float g_tab[4 * GTAB * HDIM];       // composed gaussian tables
__device__ float g_WbWe1[200 * HDIM];          // Wb @ We1[128:256]
__device__ float g_cvec[HDIM];                 // be1 + bb @ We1[128:256]
__device__ float g_W2p[HDIM * HDIM];  __device__ float g_b2p[HDIM];
__device__ float g_W3p[HDIM * HDIM];  __device__ float g_b3p[HDIM];
__device__ float g_Wn2p[HDIM * HDIM]; __device__ float g_bn2p[HDIM];
__device__ float g_sums[6][HDIM];              // [0,1]=bn1 sum/sq, [2,3]=bn2, [4,5]=bnN

// ---------------- tiny prep kernels ----------------
__global__ void zero_stats() {
    ((float*)g_sums)[threadIdx.x] = 0.0f;
}

// g_WbWe1[r][n] = sum_k Wb[r][k] * We1[128+k][n]
__global__ void wbwe1_kernel(const float* __restrict__ Wb,
                             const float* __restrict__ We1) {
    int r = blockIdx.x, n = threadIdx.x;
    float acc = 0.f;
    #pragma unroll 8
    for (int k = 0; k < 128; k++)
        acc += Wb[r * 128 + k] * We1[(128 + k) * 128 + n];
    g_WbWe1[r * 128 + n] = acc;
}

// g_cvec[n] = be1[n] + sum_k bb[k] * We1[128+k][n]
__global__ void cvec_kernel(const float* __restrict__ bb,
                            const float* __restrict__ We1,
                            const float* __restrict__ be1) {
    int n = threadIdx.x;
    float acc = be1[n];
    #pragma unroll 8
    for (int k = 0; k < 128; k++)
        acc += bb[k] * We1[(128 + k) * 128 + n];
    g_cvec[n] = acc;
}

// g_tab[(c*GTAB+g)][n] = sum_j exp(-(u_g - ctr_j)^2 * 1250) * g_WbWe1[c*50+j][n]
__global__ void table_kernel() {
    __shared__ float gs[64];
    int b = blockIdx.x;
    int c = b >> 10;            // GTAB = 1024
    int gi = b & (GTAB - 1);
    float u = (float)gi * (1.0f / (GTAB - 1));
    int tid = threadIdx.x;
    if (tid < 50) {
        float d = u - (float)tid * (1.0f / 49.0f);
        gs[tid] = __expf(-d * d * 1250.0f);
    }
    __syncthreads();
    float acc = 0.f;
    #pragma unroll
    for (int j = 0; j < 50; j++)
        acc += gs[j] * g_WbWe1[(c * 50 + j) * 128 + tid];
    g_tab[b * 128 + tid] = acc;
}

// Fold BN (stats at sidx) into next GEMM: Wdst = diag(s) Wsrc, bdst = t@Wsrc + be
__global__ void fold_kernel(int sidx, float invM,
                            const float* __restrict__ gamma,
                            const float* __restrict__ beta,
                            const float* __restrict__ Wsrc,
                            const float* __restrict__ be) {
    float* Wdst = (sidx == 0) ? g_W2p : (sidx == 2) ? g_W3p : g_Wn2p;
    float* bdst = (sidx == 0) ? g_b2p : (sidx == 2) ? g_b3p : g_bn2p;
    int n = threadIdx.x;
    if (blockIdx.x < 128) {
        int k = blockIdx.x;
        float m = g_sums[sidx][k] * invM;
        float var = g_sums[sidx + 1][k] * invM - m * m;
        float s = gamma[k] * rsqrtf(var + EPSBN);
        Wdst[k * 128 + n] = s * Wsrc[k * 128 + n];
    } else {
        float acc = be[n];
        for (int k = 0; k < 128; k++) {
            float m = g_sums[sidx][k] * invM;
            float var = g_sums[sidx + 1][k] * invM - m * m;
            float s = gamma[k] * rsqrtf(var + EPSBN);
            float t = beta[k] - m * s;
            acc += t * Wsrc[k * 128 + n];
        }
        bdst[n] = acc;
    }
}

// ---------------- fused E1: a1 = lrelu(xtop[src] + xbot[dst] + table(ea) + cvec) ----------------
__global__ __launch_bounds__(128)
void e1_fuse_kernel(const float* __restrict__ ea, const int* __restrict__ eidx) {
    int t = threadIdx.x;
    int e0 = blockIdx.x * EPB;
    float cv = g_cvec[t];
    float csum = 0.f, csq = 0.f;
    int eend = e0 + EPB;
    if (eend > NEDGE) eend = NEDGE;
    #pragma unroll 4
    for (int e = e0; e < eend; e++) {
        int s = __ldg(eidx + e);
        int d = __ldg(eidx + NEDGE + e);
        float val = g_xtop[(size_t)s * 128 + t] + g_xbot[(size_t)d * 128 + t] + cv;
        #pragma unroll
        for (int c = 0; c < 4; c++) {
            float f = __ldg(ea + (size_t)e * 4 + c);
            float p = f * (float)(GTAB - 1);
            int i0 = (int)p;
            if (i0 < 0) i0 = 0;
            if (i0 > GTAB - 2) i0 = GTAB - 2;
            float w = p - (float)i0;
            const float* t0 = g_tab + ((size_t)(c * GTAB + i0) * 128 + t);
            float u = t0[0], v2 = t0[128];
            val += u + w * (v2 - u);
        }
        val = (val >= 0.f) ? val : 0.01f * val;
        g_a1[(size_t)e * 128 + t] = val;
        csum += val;
        csq  += val * val;
    }
    atomicAdd(&g_sums[0][t], csum);
    atomicAdd(&g_sums[1][t], csq);
}

// ---------------- main tiled GEMM (128x128 tile, 256 threads, 8x8/thread) ----------------
enum { M_XD = 0, M_PLAIN = 1, M_E2 = 2, M_E3 = 3, M_N1 = 4, M_OUT = 5 };

template <int MODE>
__global__ __launch_bounds__(256)
void gemm_kernel(const float* __restrict__ A, const float* __restrict__ Wparam,
                 const float* __restrict__ biasExt,
                 const float* __restrict__ x, const float* __restrict__ ea,
                 const int* __restrict__ eidx, const float* __restrict__ vparam,
                 float* __restrict__ outp, int M) {
    __shared__ float As[16][132];
    __shared__ float Ws[16][132];

    const int tid = threadIdx.x;
    const int blockRow = blockIdx.x * 128;
    const int tr = tid >> 4;
    const int tc = tid & 15;
    const int c0 = tc * 8;

    const float* W = (MODE == M_E2) ? g_W2p
                   : (MODE == M_E3) ? g_W3p
                   : (MODE == M_OUT) ? g_Wn2p : Wparam;
    const float* bias = (MODE == M_E2) ? g_b2p
                      : (MODE == M_E3) ? g_b3p
                      : (MODE == M_OUT) ? g_bn2p : biasExt;
    const float* Aeff = (MODE == M_E2) ? g_a1
                      : (MODE == M_E3) ? g_a2
                      : (MODE == M_N1) ? g_z
                      : (MODE == M_OUT) ? g_an : A;

    // loader roles: 2 threads per row, 8 floats each
    const int lr = tid >> 1;
    const int lh = (tid & 1) * 8;
    const float* arow;
    {
        int r = blockRow + lr;
        if (r > M - 1) r = M - 1;
        arow = Aeff + (size_t)r * 128;
    }

    float acc[8][8];
    #pragma unroll
    for (int i = 0; i < 8; i++)
        #pragma unroll
        for (int j = 0; j < 8; j++) acc[i][j] = 0.f;

    #pragma unroll 1
    for (int k0 = 0; k0 < 128; k0 += 16) {
        const float* ap = arow + k0 + lh;
        float4 a0 = *(const float4*)ap;
        float4 a1 = *(const float4*)(ap + 4);

        int krow = k0 + tr;
        float4 b0 = *(const float4*)(W + (size_t)krow * 128 + c0);
        float4 b1 = *(const float4*)(W + (size_t)krow * 128 + c0 + 4);

        __syncthreads();
        As[lh + 0][lr] = a0.x; As[lh + 1][lr] = a0.y;
        As[lh + 2][lr] = a0.z; As[lh + 3][lr] = a0.w;
        As[lh + 4][lr] = a1.x; As[lh + 5][lr] = a1.y;
        As[lh + 6][lr] = a1.z; As[lh + 7][lr] = a1.w;
        *(float4*)&Ws[tr][c0]     = b0;
        *(float4*)&Ws[tr][c0 + 4] = b1;
        __syncthreads();

        #pragma unroll
        for (int kk = 0; kk < 16; kk++) {
            float af[8], bf[8];
            *(float4*)(af)     = *(const float4*)&As[kk][tr * 8];
            *(float4*)(af + 4) = *(const float4*)&As[kk][tr * 8 + 4];
            *(float4*)(bf)     = *(const float4*)&Ws[kk][c0];
            *(float4*)(bf + 4) = *(const float4*)&Ws[kk][c0 + 4];
            #pragma unroll
            for (int i = 0; i < 8; i++)
                #pragma unroll
                for (int j = 0; j < 8; j++)
                    acc[i][j] += af[i] * bf[j];
        }
    }
    __syncthreads();   // smem free for epilogue reductions

    float bj[8];
    #pragma unroll
    for (int j = 0; j < 8; j++) bj[j] = (MODE == M_PLAIN) ? 0.f : bias[c0 + j];

    // ------------- epilogues -------------
    if (MODE == M_PLAIN) {
        #pragma unroll
        for (int i = 0; i < 8; i++) {
            int r = blockRow + tr * 8 + i;
            if (r >= M) break;
            float* dp = outp + (size_t)r * 128 + c0;
            *(float4*)dp       = make_float4(acc[i][0], acc[i][1], acc[i][2], acc[i][3]);
            *(float4*)(dp + 4) = make_float4(acc[i][4], acc[i][5], acc[i][6], acc[i][7]);
        }
        return;
    }

    if (MODE == M_XD) {
        float vj[8];
        #pragma unroll
        for (int j = 0; j < 8; j++) vj[j] = vparam[c0 + j];
        #pragma unroll
        for (int i = 0; i < 8; i++) {
            int r = blockRow + tr * 8 + i;
            if (r >= M) break;
            float vals[8], zv[8];
            #pragma unroll
            for (int j = 0; j < 8; j++) { vals[j] = acc[i][j] + bj[j]; zv[j] = vj[j] * vals[j]; }
            float* dp = g_xd + (size_t)r * 128 + c0;
            *(float4*)dp       = make_float4(vals[0], vals[1], vals[2], vals[3]);
            *(float4*)(dp + 4) = make_float4(vals[4], vals[5], vals[6], vals[7]);
            float* zp = g_z + (size_t)r * 128 + c0;
            *(float4*)zp       = make_float4(zv[0], zv[1], zv[2], zv[3]);
            *(float4*)(zp + 4) = make_float4(zv[4], zv[5], zv[6], zv[7]);
        }
        return;
    }

    if (MODE == M_E3) {
        #pragma unroll 1
        for (int i = 0; i < 8; i++) {
            int r = blockRow + tr * 8 + i;
            if (r >= M) break;
            int s_ = eidx[r], d_ = eidx[NEDGE + r];
            float coeff = cosf(1.5707963267948966f * ea[(size_t)r * 4 + 3]);
            const float* xp = g_xd + (size_t)s_ * 128 + c0;
            float4 x0 = *(const float4*)xp;
            float4 x1 = *(const float4*)(xp + 4);
            float v0 = coeff * (acc[i][0] + bj[0]) * x0.x;
            float v1 = coeff * (acc[i][1] + bj[1]) * x0.y;
            float v2 = coeff * (acc[i][2] + bj[2]) * x0.z;
            float v3 = coeff * (acc[i][3] + bj[3]) * x0.w;
            float v4 = coeff * (acc[i][4] + bj[4]) * x1.x;
            float v5 = coeff * (acc[i][5] + bj[5]) * x1.y;
            float v6 = coeff * (acc[i][6] + bj[6]) * x1.z;
            float v7 = coeff * (acc[i][7] + bj[7]) * x1.w;
            float* zp = g_z + (size_t)d_ * 128 + c0;
            asm volatile("red.global.add.v4.f32 [%0], {%1,%2,%3,%4};"
                         :: "l"(zp), "f"(v0), "f"(v1), "f"(v2), "f"(v3) : "memory");
            asm volatile("red.global.add.v4.f32 [%0], {%1,%2,%3,%4};"
                         :: "l"(zp + 4), "f"(v4), "f"(v5), "f"(v6), "f"(v7) : "memory");
        }
        return;
    }

    if (MODE == M_OUT) {
        #pragma unroll
        for (int i = 0; i < 8; i++) {
            int r = blockRow + tr * 8 + i;
            if (r >= M) break;
            const float* xp = x + (size_t)r * 128 + c0;
            float4 x0 = *(const float4*)xp;
            float4 x1 = *(const float4*)(xp + 4);
            float vals[8];
            vals[0] = acc[i][0] + bj[0] + x0.x; vals[1] = acc[i][1] + bj[1] + x0.y;
            vals[2] = acc[i][2] + bj[2] + x0.z; vals[3] = acc[i][3] + bj[3] + x0.w;
            vals[4] = acc[i][4] + bj[4] + x1.x; vals[5] = acc[i][5] + bj[5] + x1.y;
            vals[6] = acc[i][6] + bj[6] + x1.z; vals[7] = acc[i][7] + bj[7] + x1.w;
            float* dp = outp + (size_t)r * 128 + c0;
            *(float4*)dp       = make_float4(vals[0], vals[1], vals[2], vals[3]);
            *(float4*)(dp + 4) = make_float4(vals[4], vals[5], vals[6], vals[7]);
        }
        return;
    }

    // M_E2 / M_N1: lrelu + store raw + batch stats
    {
        constexpr int SIDX = (MODE == M_E2) ? 2 : 4;
        float* dst = (MODE == M_E2) ? g_a2 : g_an;
        float csum[8], csq[8];
        #pragma unroll
        for (int j = 0; j < 8; j++) { csum[j] = 0.f; csq[j] = 0.f; }

        #pragma unroll 1
        for (int i = 0; i < 8; i++) {
            int r = blockRow + tr * 8 + i;
            if (r >= M) break;
            float vals[8];
            #pragma unroll
            for (int j = 0; j < 8; j++) {
                float v_ = acc[i][j] + bj[j];
                v_ = (v_ >= 0.f) ? v_ : 0.01f * v_;
                vals[j] = v_;
                csum[j] += v_;
                csq[j]  += v_ * v_;
            }
            float* dp = dst + (size_t)r * 128 + c0;
            *(float4*)dp       = make_float4(vals[0], vals[1], vals[2], vals[3]);
            *(float4*)(dp + 4) = make_float4(vals[4], vals[5], vals[6], vals[7]);
        }

        // block-level column reduction, then one atomic per column
        #pragma unroll
        for (int j = 0; j < 8; j++) As[tr][c0 + j] = csum[j];
        __syncthreads();
        if (tid < 128) {
            float s = 0.f;
            #pragma unroll
            for (int t = 0; t < 16; t++) s += As[t][tid];
            atomicAdd(&g_sums[SIDX][tid], s);
        }
        __syncthreads();
        #pragma unroll
        for (int j = 0; j < 8; j++) As[tr][c0 + j] = csq[j];
        __syncthreads();
        if (tid < 128) {
            float s = 0.f;
            #pragma unroll
            for (int t = 0; t < 16; t++) s += As[t][tid];
            atomicAdd(&g_sums[SIDX + 1][tid], s);
        }
    }
}

// ---------------- launcher ----------------
extern "C" void kernel_launch(void* const* d_in, const int* in_sizes, int n_in,
                              void* d_out, int out_size) {
    const float* x    = (const float*)d_in[0];
    const float* ea   = (const float*)d_in[1];
    const int*   eidx = (const int*)  d_in[2];
    const float* Wb   = (const float*)d_in[3];
    const float* bb   = (const float*)d_in[4];
    const float* We1  = (const float*)d_in[5];
    const float* be1  = (const float*)d_in[6];
    const float* ge1  = (const float*)d_in[7];
    const float* bte1 = (const float*)d_in[8];
    const float* We2  = (const float*)d_in[9];
    const float* be2  = (const float*)d_in[10];
    const float* ge2  = (const float*)d_in[11];
    const float* bte2 = (const float*)d_in[12];
    const float* We3  = (const float*)d_in[13];
    const float* be3  = (const float*)d_in[14];
    const float* Wd   = (const float*)d_in[15];
    const float* bd   = (const float*)d_in[16];
    const float* v    = (const float*)d_in[17];
    const float* Wn1  = (const float*)d_in[18];
    const float* bn1  = (const float*)d_in[19];
    const float* gn   = (const float*)d_in[20];
    const float* btn  = (const float*)d_in[21];
    const float* Wn2  = (const float*)d_in[22];
    const float* bn2  = (const float*)d_in[23];
    float* outp = (float*)d_out;

    const int gridE = (NEDGE + 127) / 128;   // 2344
    const int gridN = (NNODE + 127) / 128;   // 391

    float* d_xtop; cudaGetSymbolAddress((void**)&d_xtop, g_xtop);
    float* d_xbot; cudaGetSymbolAddress((void**)&d_xbot, g_xbot);

    zero_stats<<<1, 768>>>();
    wbwe1_kernel<<<200, 128>>>(Wb, We1);
    cvec_kernel<<<1, 128>>>(bb, We1, be1);
    table_kernel<<<4 * GTAB, 128>>>();

    // xd = x@Wd + bd ; z = v * xd
    gemm_kernel<M_XD><<<gridN, 256>>>(x, Wd, bd, nullptr, nullptr, nullptr, v, nullptr, NNODE);

    // xtop = x @ We1[0:128] ; xbot = x @ We1[256:384]   (no bias; be1 folded into cvec)
    gemm_kernel<M_PLAIN><<<gridN, 256>>>(x, We1,             nullptr, nullptr, nullptr, nullptr, nullptr, d_xtop, NNODE);
    gemm_kernel<M_PLAIN><<<gridN, 256>>>(x, We1 + 256 * 128, nullptr, nullptr, nullptr, nullptr, nullptr, d_xbot, NNODE);

    // a1 = lrelu(xtop[src] + xbot[dst] + table(ea) + cvec), stats -> [0,1]
    e1_fuse_kernel<<<(NEDGE + EPB - 1) / EPB, 128>>>(ea, eidx);
    fold_kernel<<<129, 128>>>(0, 1.0f / NEDGE, ge1, bte1, We2, be2);

    // a2 = lrelu(a1@W2p + b2p), stats -> [2,3]
    gemm_kernel<M_E2><<<gridE, 256>>>(nullptr, nullptr, nullptr, nullptr, nullptr, nullptr, nullptr, nullptr, NEDGE);
    fold_kernel<<<129, 128>>>(2, 1.0f / NEDGE, ge2, bte2, We3, be3);

    // scatter: z[dst] += cos(pi/2*ea3) * (a2@W3p + b3p) * xd[src]
    gemm_kernel<M_E3><<<gridE, 256>>>(nullptr, nullptr, nullptr, nullptr, ea, eidx, nullptr, nullptr, NEDGE);

    // an = lrelu(z@Wn1 + bn1), stats -> [4,5]
    gemm_kernel<M_N1><<<gridN, 256>>>(nullptr, Wn1, bn1, nullptr, nullptr, nullptr, nullptr, nullptr, NNODE);
    fold_kernel<<<129, 128>>>(4, 1.0f / NNODE, gn, btn, Wn2, bn2);

    // out = an@Wn2p + bn2p + x
    gemm_kernel<M_OUT><<<gridN, 256>>>(nullptr, nullptr, nullptr, x, nullptr, nullptr, nullptr, outp, NNODE);
}

// round 4
// speedup vs baseline: 1.8916x; 1.3226x over previous
#include <cuda_runtime.h>
#include <cuda_bf16.h>

#define NNODE 50000
#define NEDGE 300000
#define GTAB  1024
#define EPSBN 1e-5f
#define NTILE 2344              // ceil(NEDGE/128)
#define ROWB  272               // padded smem row bytes (136 bf16)
#define TCSM  (4 * 128 * ROWB)  // 139264: Ah|Al|Wh|Wl

// ---------------- scratch (device globals; no allocation) ----------------
__device__ uint4 g_a1split[(size_t)NTILE * 4096];  // per tile: 32KB bf16-hi | 32KB bf16-lo, row-major [m][k]
__device__ uint4 g_a2split[(size_t)NTILE * 4096];
__device__ uint4 g_W2s[4096];                      // 64KB: W^T [n][k] hi | lo
__device__ uint4 g_W3s[4096];
__device__ float g_xd[(size_t)NNODE * 128];
__device__ float g_z [(size_t)NNODE * 128];
__device__ float g_an[(size_t)NNODE * 128];
__device__ float g_xtop[(size_t)NNODE * 128];
__device__ float g_xbot[(size_t)NNODE * 128];
__device__ float g_tab[4 * GTAB * 128];
__device__ float g_WbWe1[200 * 128];
__device__ float g_cvec[128];
__device__ float g_W2p[128 * 128];  __device__ float g_b2p[128];
__device__ float g_W3p[128 * 128];  __device__ float g_b3p[128];
__device__ float g_Wn2p[128 * 128]; __device__ float g_bn2p[128];
__device__ float g_sums[6][128];

// ---------------- helpers ----------------
__device__ __forceinline__ unsigned smem_u32(const void* p) {
    unsigned a;
    asm("{ .reg .u64 t; cvta.to.shared.u64 t, %1; cvt.u32.u64 %0, t; }" : "=r"(a) : "l"(p));
    return a;
}
#define LDMX4(r, addr)                                                         \
    asm volatile("ldmatrix.sync.aligned.m8n8.x4.shared.b16 {%0,%1,%2,%3}, [%4];" \
                 : "=r"((r)[0]), "=r"((r)[1]), "=r"((r)[2]), "=r"((r)[3])      \
                 : "r"(addr))
#define MMA_BF16(d, a0, a1, a2, a3, b0, b1)                                    \
    asm volatile("mma.sync.aligned.m16n8k16.row.col.f32.bf16.bf16.f32 "        \
                 "{%0,%1,%2,%3}, {%4,%5,%6,%7}, {%8,%9}, {%0,%1,%2,%3};"       \
                 : "+f"((d)[0]), "+f"((d)[1]), "+f"((d)[2]), "+f"((d)[3])      \
                 : "r"(a0), "r"(a1), "r"(a2), "r"(a3), "r"(b0), "r"(b1))

// ---------------- tiny prep kernels ----------------
__global__ void zero_stats() { ((float*)g_sums)[threadIdx.x] = 0.0f; }

__global__ void wbwe1_kernel(const float* __restrict__ Wb, const float* __restrict__ We1) {
    int r = blockIdx.x, n = threadIdx.x;
    float acc = 0.f;
    #pragma unroll 8
    for (int k = 0; k < 128; k++) acc += Wb[r * 128 + k] * We1[(128 + k) * 128 + n];
    g_WbWe1[r * 128 + n] = acc;
}

__global__ void cvec_kernel(const float* __restrict__ bb, const float* __restrict__ We1,
                            const float* __restrict__ be1) {
    int n = threadIdx.x;
    float acc = be1[n];
    #pragma unroll 8
    for (int k = 0; k < 128; k++) acc += bb[k] * We1[(128 + k) * 128 + n];
    g_cvec[n] = acc;
}

__global__ void table_kernel() {
    __shared__ float gs[64];
    int b = blockIdx.x;
    int c = b >> 10;
    int gi = b & (GTAB - 1);
    float u = (float)gi * (1.0f / (GTAB - 1));
    int tid = threadIdx.x;
    if (tid < 50) {
        float d = u - (float)tid * (1.0f / 49.0f);
        gs[tid] = __expf(-d * d * 1250.0f);
    }
    __syncthreads();
    float acc = 0.f;
    #pragma unroll
    for (int j = 0; j < 50; j++) acc += gs[j] * g_WbWe1[(c * 50 + j) * 128 + tid];
    g_tab[b * 128 + tid] = acc;
}

__global__ void fold_kernel(int sidx, float invM,
                            const float* __restrict__ gamma, const float* __restrict__ beta,
                            const float* __restrict__ Wsrc, const float* __restrict__ be) {
    float* Wdst = (sidx == 0) ? g_W2p : (sidx == 2) ? g_W3p : g_Wn2p;
    float* bdst = (sidx == 0) ? g_b2p : (sidx == 2) ? g_b3p : g_bn2p;
    int n = threadIdx.x;
    if (blockIdx.x < 128) {
        int k = blockIdx.x;
        float m = g_sums[sidx][k] * invM;
        float var = g_sums[sidx + 1][k] * invM - m * m;
        float s = gamma[k] * rsqrtf(var + EPSBN);
        Wdst[k * 128 + n] = s * Wsrc[k * 128 + n];
    } else {
        float acc = be[n];
        for (int k = 0; k < 128; k++) {
            float m = g_sums[sidx][k] * invM;
            float var = g_sums[sidx + 1][k] * invM - m * m;
            float s = gamma[k] * rsqrtf(var + EPSBN);
            acc += (beta[k] - m * s) * Wsrc[k * 128 + n];
        }
        bdst[n] = acc;
    }
}

// Pack W^T ([n][k] row-major) into bf16 hi/lo staging (64KB)
__global__ void pack_kernel(const float* __restrict__ Wp, char* __restrict__ Ws) {
    int n = blockIdx.x, k = threadIdx.x;
    float v = Wp[k * 128 + n];
    float h = __bfloat162float(__float2bfloat16_rn(v));
    int off = n * 256 + 2 * k;
    *(unsigned short*)(Ws + off)         = __bfloat16_as_ushort(__float2bfloat16_rn(h));
    *(unsigned short*)(Ws + 32768 + off) = __bfloat16_as_ushort(__float2bfloat16_rn(v - h));
}

// ---------------- fused E1 -> bf16 hi/lo tiles + stats ----------------
__global__ __launch_bounds__(128)
void e1_fuse_kernel(const float* __restrict__ ea, const int* __restrict__ eidx) {
    int t = threadIdx.x;
    int e0 = blockIdx.x * 128;
    char* tb = (char*)g_a1split + (size_t)blockIdx.x * 65536;
    float cv = g_cvec[t];
    float csum = 0.f, csq = 0.f;
    int eend = e0 + 128;
    if (eend > NEDGE) eend = NEDGE;
    for (int e = e0; e < eend; e++) {
        int s = __ldg(eidx + e);
        int d = __ldg(eidx + NEDGE + e);
        float val = g_xtop[(size_t)s * 128 + t] + g_xbot[(size_t)d * 128 + t] + cv;
        #pragma unroll
        for (int c = 0; c < 4; c++) {
            float f = __ldg(ea + (size_t)e * 4 + c);
            float p = f * (float)(GTAB - 1);
            int i0 = (int)p;
            if (i0 < 0) i0 = 0;
            if (i0 > GTAB - 2) i0 = GTAB - 2;
            float w = p - (float)i0;
            const float* t0 = g_tab + ((size_t)(c * GTAB + i0) * 128 + t);
            float u = t0[0], v2 = t0[128];
            val += u + w * (v2 - u);
        }
        val = (val >= 0.f) ? val : 0.01f * val;
        csum += val; csq += val * val;
        float h = __bfloat162float(__float2bfloat16_rn(val));
        int off = (e - e0) * 256 + 2 * t;
        *(unsigned short*)(tb + off)         = __bfloat16_as_ushort(__float2bfloat16_rn(h));
        *(unsigned short*)(tb + 32768 + off) = __bfloat16_as_ushort(__float2bfloat16_rn(val - h));
    }
    for (int e = eend; e < e0 + 128; e++) {
        int off = (e - e0) * 256 + 2 * t;
        *(unsigned short*)(tb + off) = 0;
        *(unsigned short*)(tb + 32768 + off) = 0;
    }
    atomicAdd(&g_sums[0][t], csum);
    atomicAdd(&g_sums[1][t], csq);
}

// ---------------- bf16 tensor-core edge GEMMs (mma.sync): MODE 0 = E2, MODE 1 = E3 ----------------
template <int MODE>
__global__ __launch_bounds__(256)
void tc_gemm(const float* __restrict__ ea, const int* __restrict__ eidx) {
    extern __shared__ char sm[];
    const int tid = threadIdx.x;
    const int lane = tid & 31, wid = tid >> 5;
    const int wm = wid & 3, wn = wid >> 2;

    const unsigned sAh_u = smem_u32(sm);
    const unsigned sAl_u = sAh_u + 128 * ROWB;
    const unsigned sWh_u = sAh_u + 2 * 128 * ROWB;
    const unsigned sWl_u = sAh_u + 3 * 128 * ROWB;

    // ---- load tiles (gmem row-major [r][k] bf16, 256B rows) -> smem padded rows ----
    const uint4* Asrc = (MODE == 0 ? g_a1split : g_a2split) + (size_t)blockIdx.x * 4096;
    const uint4* Wsrc = (MODE == 0 ? g_W2s : g_W3s);
    {
        char* sAh = sm;
        char* sAl = sm + 128 * ROWB;
        char* sWh = sm + 2 * 128 * ROWB;
        char* sWl = sm + 3 * 128 * ROWB;
        #pragma unroll
        for (int i = tid; i < 2048; i += 256) {
            int row = i >> 4, ch = i & 15;
            *(uint4*)(sAh + row * ROWB + ch * 16) = Asrc[i];
            *(uint4*)(sAl + row * ROWB + ch * 16) = Asrc[i + 2048];
            *(uint4*)(sWh + row * ROWB + ch * 16) = Wsrc[i];
            *(uint4*)(sWl + row * ROWB + ch * 16) = Wsrc[i + 2048];
        }
    }
    __syncthreads();

    // ---- mma mainloop: 3 products (Ah*Wh + Al*Wh + Ah*Wl), K=128 ----
    const int laneRow = lane & 15;
    const unsigned laneK = (unsigned)((lane >> 4) << 4);
    const unsigned aoff = (unsigned)((wm * 32 + laneRow) * ROWB) + laneK;
    const unsigned woff = (unsigned)((wn * 64 + laneRow) * ROWB) + laneK;

    float acc[2][8][4];
    #pragma unroll
    for (int t = 0; t < 2; t++)
        #pragma unroll
        for (int n = 0; n < 8; n++)
            #pragma unroll
            for (int q = 0; q < 4; q++) acc[t][n][q] = 0.f;

    #pragma unroll 1
    for (int ks = 0; ks < 8; ks++) {
        unsigned kb = (unsigned)(ks * 32);
        unsigned ah[2][4], al[2][4], bw[4][4];
        LDMX4(ah[0], sAh_u + aoff + kb);
        LDMX4(ah[1], sAh_u + aoff + 16 * ROWB + kb);
        LDMX4(al[0], sAl_u + aoff + kb);
        LDMX4(al[1], sAl_u + aoff + 16 * ROWB + kb);
        #pragma unroll
        for (int p = 0; p < 4; p++)
            LDMX4(bw[p], sWh_u + woff + p * 16 * ROWB + kb);
        #pragma unroll
        for (int t = 0; t < 2; t++)
            #pragma unroll
            for (int p = 0; p < 4; p++) {
                MMA_BF16(acc[t][2 * p],     ah[t][0], ah[t][1], ah[t][2], ah[t][3], bw[p][0], bw[p][2]);
                MMA_BF16(acc[t][2 * p + 1], ah[t][0], ah[t][1], ah[t][2], ah[t][3], bw[p][1], bw[p][3]);
            }
        #pragma unroll
        for (int t = 0; t < 2; t++)
            #pragma unroll
            for (int p = 0; p < 4; p++) {
                MMA_BF16(acc[t][2 * p],     al[t][0], al[t][1], al[t][2], al[t][3], bw[p][0], bw[p][2]);
                MMA_BF16(acc[t][2 * p + 1], al[t][0], al[t][1], al[t][2], al[t][3], bw[p][1], bw[p][3]);
            }
        #pragma unroll
        for (int p = 0; p < 4; p++)
            LDMX4(bw[p], sWl_u + woff + p * 16 * ROWB + kb);
        #pragma unroll
        for (int t = 0; t < 2; t++)
            #pragma unroll
            for (int p = 0; p < 4; p++) {
                MMA_BF16(acc[t][2 * p],     ah[t][0], ah[t][1], ah[t][2], ah[t][3], bw[p][0], bw[p][2]);
                MMA_BF16(acc[t][2 * p + 1], ah[t][0], ah[t][1], ah[t][2], ah[t][3], bw[p][1], bw[p][3]);
            }
    }
    __syncthreads();   // done reading smem tiles; reuse as fp32 stage

    // ---- stage D into smem fp32 [128][132] ----
    float* sF = (float*)sm;
    {
        int mr = lane >> 2;
        int nc = 2 * (lane & 3);
        #pragma unroll
        for (int t = 0; t < 2; t++) {
            int row = wm * 32 + t * 16 + mr;
            #pragma unroll
            for (int nt = 0; nt < 8; nt++) {
                int col = wn * 64 + nt * 8 + nc;
                sF[row * 132 + col]           = acc[t][nt][0];
                sF[row * 132 + col + 1]       = acc[t][nt][1];
                sF[(row + 8) * 132 + col]     = acc[t][nt][2];
                sF[(row + 8) * 132 + col + 1] = acc[t][nt][3];
            }
        }
    }
    __syncthreads();

    if (MODE == 0) {
        // column-owner: bias + lrelu + stats + bf16 hi/lo repack to g_a2split
        int c = tid & 127, h = tid >> 7;
        float bc = g_b2p[c];
        char* outb = (char*)g_a2split + (size_t)blockIdx.x * 65536;
        long gbase = (long)blockIdx.x * 128;
        float s0 = 0.f, s1 = 0.f;
        #pragma unroll 4
        for (int r = 0; r < 64; r++) {
            int rl = h * 64 + r;
            bool valid = (gbase + rl) < NEDGE;
            float v = sF[rl * 132 + c] + bc;
            v = (v >= 0.f) ? v : 0.01f * v;
            if (!valid) v = 0.f;
            s0 += v; s1 += v * v;
            float hh = __bfloat162float(__float2bfloat16_rn(v));
            int off = rl * 256 + 2 * c;
            *(unsigned short*)(outb + off)         = __bfloat16_as_ushort(__float2bfloat16_rn(hh));
            *(unsigned short*)(outb + 32768 + off) = __bfloat16_as_ushort(__float2bfloat16_rn(v - hh));
        }
        atomicAdd(&g_sums[2][c], s0);
        atomicAdd(&g_sums[3][c], s1);
    } else {
        // row-owner halves: z[dst] += coeff * (D + b3p) * xd[src]
        int rt = tid >> 1, h = tid & 1;
        long grow = (long)blockIdx.x * 128 + rt;
        if (grow < NEDGE) {
            int s_ = eidx[grow], d_ = eidx[NEDGE + grow];
            float coeff = cosf(1.5707963267948966f * ea[grow * 4 + 3]);
            const float4* xp = (const float4*)(g_xd + (size_t)s_ * 128) + h * 16;
            const float4* bp = (const float4*)g_b3p + h * 16;
            float* zp = g_z + (size_t)d_ * 128 + h * 64;
            const float* fr = sF + rt * 132 + h * 64;
            #pragma unroll
            for (int q = 0; q < 16; q++) {
                float4 xv = xp[q];
                float4 bv = bp[q];
                float v0 = coeff * (fr[4 * q + 0] + bv.x) * xv.x;
                float v1 = coeff * (fr[4 * q + 1] + bv.y) * xv.y;
                float v2 = coeff * (fr[4 * q + 2] + bv.z) * xv.z;
                float v3 = coeff * (fr[4 * q + 3] + bv.w) * xv.w;
                asm volatile("red.global.add.v4.f32 [%0], {%1,%2,%3,%4};"
                             :: "l"(zp + 4 * q), "f"(v0), "f"(v1), "f"(v2), "f"(v3) : "memory");
            }
        }
    }
}

// ---------------- SIMT node GEMMs (128x128 tile, 256 threads) ----------------
enum { M_XD = 0, M_PLAIN = 1, M_N1 = 4, M_OUT = 5 };

template <int MODE>
__global__ __launch_bounds__(256)
void gemm_kernel(const float* __restrict__ A, const float* __restrict__ Wparam,
                 const float* __restrict__ biasExt, const float* __restrict__ x,
                 const float* __restrict__ vparam, float* __restrict__ outp, int M) {
    __shared__ float As[16][132];
    __shared__ float Ws[16][132];

    const int tid = threadIdx.x;
    const int blockRow = blockIdx.x * 128;
    const int tr = tid >> 4;
    const int tc = tid & 15;
    const int c0 = tc * 8;

    const float* W = (MODE == M_OUT) ? g_Wn2p : Wparam;
    const float* bias = (MODE == M_OUT) ? g_bn2p : biasExt;
    const float* Aeff = (MODE == M_N1) ? g_z : (MODE == M_OUT) ? g_an : A;

    const int lr = tid >> 1;
    const int lh = (tid & 1) * 8;
    const float* arow;
    {
        int r = blockRow + lr;
        if (r > M - 1) r = M - 1;
        arow = Aeff + (size_t)r * 128;
    }

    float acc[8][8];
    #pragma unroll
    for (int i = 0; i < 8; i++)
        #pragma unroll
        for (int j = 0; j < 8; j++) acc[i][j] = 0.f;

    #pragma unroll 1
    for (int k0 = 0; k0 < 128; k0 += 16) {
        const float* ap = arow + k0 + lh;
        float4 a0 = *(const float4*)ap;
        float4 a1 = *(const float4*)(ap + 4);
        int krow = k0 + tr;
        float4 b0 = *(const float4*)(W + (size_t)krow * 128 + c0);
        float4 b1 = *(const float4*)(W + (size_t)krow * 128 + c0 + 4);

        __syncthreads();
        As[lh + 0][lr] = a0.x; As[lh + 1][lr] = a0.y;
        As[lh + 2][lr] = a0.z; As[lh + 3][lr] = a0.w;
        As[lh + 4][lr] = a1.x; As[lh + 5][lr] = a1.y;
        As[lh + 6][lr] = a1.z; As[lh + 7][lr] = a1.w;
        *(float4*)&Ws[tr][c0]     = b0;
        *(float4*)&Ws[tr][c0 + 4] = b1;
        __syncthreads();

        #pragma unroll
        for (int kk = 0; kk < 16; kk++) {
            float af[8], bf[8];
            *(float4*)(af)     = *(const float4*)&As[kk][tr * 8];
            *(float4*)(af + 4) = *(const float4*)&As[kk][tr * 8 + 4];
            *(float4*)(bf)     = *(const float4*)&Ws[kk][c0];
            *(float4*)(bf + 4) = *(const float4*)&Ws[kk][c0 + 4];
            #pragma unroll
            for (int i = 0; i < 8; i++)
                #pragma unroll
                for (int j = 0; j < 8; j++)
                    acc[i][j] += af[i] * bf[j];
        }
    }
    __syncthreads();

    float bj[8];
    #pragma unroll
    for (int j = 0; j < 8; j++) bj[j] = (MODE == M_PLAIN) ? 0.f : bias[c0 + j];

    if (MODE == M_PLAIN) {
        #pragma unroll
        for (int i = 0; i < 8; i++) {
            int r = blockRow + tr * 8 + i;
            if (r >= M) break;
            float* dp = outp + (size_t)r * 128 + c0;
            *(float4*)dp       = make_float4(acc[i][0], acc[i][1], acc[i][2], acc[i][3]);
            *(float4*)(dp + 4) = make_float4(acc[i][4], acc[i][5], acc[i][6], acc[i][7]);
        }
        return;
    }
    if (MODE == M_XD) {
        float vj[8];
        #pragma unroll
        for (int j = 0; j < 8; j++) vj[j] = vparam[c0 + j];
        #pragma unroll
        for (int i = 0; i < 8; i++) {
            int r = blockRow + tr * 8 + i;
            if (r >= M) break;
            float vals[8], zv[8];
            #pragma unroll
            for (int j = 0; j < 8; j++) { vals[j] = acc[i][j] + bj[j]; zv[j] = vj[j] * vals[j]; }
            float* dp = g_xd + (size_t)r * 128 + c0;
            *(float4*)dp       = make_float4(vals[0], vals[1], vals[2], vals[3]);
            *(float4*)(dp + 4) = make_float4(vals[4], vals[5], vals[6], vals[7]);
            float* zp = g_z + (size_t)r * 128 + c0;
            *(float4*)zp       = make_float4(zv[0], zv[1], zv[2], zv[3]);
            *(float4*)(zp + 4) = make_float4(zv[4], zv[5], zv[6], zv[7]);
        }
        return;
    }
    if (MODE == M_OUT) {
        #pragma unroll
        for (int i = 0; i < 8; i++) {
            int r = blockRow + tr * 8 + i;
            if (r >= M) break;
            const float* xp = x + (size_t)r * 128 + c0;
            float4 x0 = *(const float4*)xp;
            float4 x1 = *(const float4*)(xp + 4);
            float* dp = outp + (size_t)r * 128 + c0;
            *(float4*)dp = make_float4(acc[i][0] + bj[0] + x0.x, acc[i][1] + bj[1] + x0.y,
                                       acc[i][2] + bj[2] + x0.z, acc[i][3] + bj[3] + x0.w);
            *(float4*)(dp + 4) = make_float4(acc[i][4] + bj[4] + x1.x, acc[i][5] + bj[5] + x1.y,
                                             acc[i][6] + bj[6] + x1.z, acc[i][7] + bj[7] + x1.w);
        }
        return;
    }
    // M_N1: lrelu + store + stats
    {
        float csum[8], csq[8];
        #pragma unroll
        for (int j = 0; j < 8; j++) { csum[j] = 0.f; csq[j] = 0.f; }
        #pragma unroll 1
        for (int i = 0; i < 8; i++) {
            int r = blockRow + tr * 8 + i;
            if (r >= M) break;
            float vals[8];
            #pragma unroll
            for (int j = 0; j < 8; j++) {
                float v_ = acc[i][j] + bj[j];
                v_ = (v_ >= 0.f) ? v_ : 0.01f * v_;
                vals[j] = v_; csum[j] += v_; csq[j] += v_ * v_;
            }
            float* dp = g_an + (size_t)r * 128 + c0;
            *(float4*)dp       = make_float4(vals[0], vals[1], vals[2], vals[3]);
            *(float4*)(dp + 4) = make_float4(vals[4], vals[5], vals[6], vals[7]);
        }
        #pragma unroll
        for (int j = 0; j < 8; j++) As[tr][c0 + j] = csum[j];
        __syncthreads();
        if (tid < 128) {
            float s = 0.f;
            #pragma unroll
            for (int t = 0; t < 16; t++) s += As[t][tid];
            atomicAdd(&g_sums[4][tid], s);
        }
        __syncthreads();
        #pragma unroll
        for (int j = 0; j < 8; j++) As[tr][c0 + j] = csq[j];
        __syncthreads();
        if (tid < 128) {
            float s = 0.f;
            #pragma unroll
            for (int t = 0; t < 16; t++) s += As[t][tid];
            atomicAdd(&g_sums[5][tid], s);
        }
    }
}

// ---------------- launcher ----------------
extern "C" void kernel_launch(void* const* d_in, const int* in_sizes, int n_in,
                              void* d_out, int out_size) {
    const float* x    = (const float*)d_in[0];
    const float* ea   = (const float*)d_in[1];
    const int*   eidx = (const int*)  d_in[2];
    const float* Wb   = (const float*)d_in[3];
    const float* bb   = (const float*)d_in[4];
    const float* We1  = (const float*)d_in[5];
    const float* be1  = (const float*)d_in[6];
    const float* ge1  = (const float*)d_in[7];
    const float* bte1 = (const float*)d_in[8];
    const float* We2  = (const float*)d_in[9];
    const float* be2  = (const float*)d_in[10];
    const float* ge2  = (const float*)d_in[11];
    const float* bte2 = (const float*)d_in[12];
    const float* We3  = (const float*)d_in[13];
    const float* be3  = (const float*)d_in[14];
    const float* Wd   = (const float*)d_in[15];
    const float* bd   = (const float*)d_in[16];
    const float* v    = (const float*)d_in[17];
    const float* Wn1  = (const float*)d_in[18];
    const float* bn1  = (const float*)d_in[19];
    const float* gn   = (const float*)d_in[20];
    const float* btn  = (const float*)d_in[21];
    const float* Wn2  = (const float*)d_in[22];
    const float* bn2  = (const float*)d_in[23];
    float* outp = (float*)d_out;

    const int gridN = (NNODE + 127) / 128;

    float* d_xtop; cudaGetSymbolAddress((void**)&d_xtop, g_xtop);
    float* d_xbot; cudaGetSymbolAddress((void**)&d_xbot, g_xbot);
    float* d_W2p;  cudaGetSymbolAddress((void**)&d_W2p, g_W2p);
    float* d_W3p;  cudaGetSymbolAddress((void**)&d_W3p, g_W3p);
    char*  d_W2s;  cudaGetSymbolAddress((void**)&d_W2s, g_W2s);
    char*  d_W3s;  cudaGetSymbolAddress((void**)&d_W3s, g_W3s);

    cudaFuncSetAttribute(tc_gemm<0>, cudaFuncAttributeMaxDynamicSharedMemorySize, TCSM);
    cudaFuncSetAttribute(tc_gemm<1>, cudaFuncAttributeMaxDynamicSharedMemorySize, TCSM);

    zero_stats<<<1, 768>>>();
    wbwe1_kernel<<<200, 128>>>(Wb, We1);
    cvec_kernel<<<1, 128>>>(bb, We1, be1);
    table_kernel<<<4 * GTAB, 128>>>();

    gemm_kernel<M_XD><<<gridN, 256>>>(x, Wd, bd, nullptr, v, nullptr, NNODE);
    gemm_kernel<M_PLAIN><<<gridN, 256>>>(x, We1,             nullptr, nullptr, nullptr, d_xtop, NNODE);
    gemm_kernel<M_PLAIN><<<gridN, 256>>>(x, We1 + 256 * 128, nullptr, nullptr, nullptr, d_xbot, NNODE);

    e1_fuse_kernel<<<NTILE, 128>>>(ea, eidx);
    fold_kernel<<<129, 128>>>(0, 1.0f / NEDGE, ge1, bte1, We2, be2);
    pack_kernel<<<128, 128>>>(d_W2p, d_W2s);

    tc_gemm<0><<<NTILE, 256, TCSM>>>(ea, eidx);
    fold_kernel<<<129, 128>>>(2, 1.0f / NEDGE, ge2, bte2, We3, be3);
    pack_kernel<<<128, 128>>>(d_W3p, d_W3s);

    tc_gemm<1><<<NTILE, 256, TCSM>>>(ea, eidx);

    gemm_kernel<M_N1><<<gridN, 256>>>(nullptr, Wn1, bn1, nullptr, nullptr, nullptr, NNODE);
    fold_kernel<<<129, 128>>>(4, 1.0f / NNODE, gn, btn, Wn2, bn2);
    gemm_kernel<M_OUT><<<gridN, 256>>>(nullptr, nullptr, nullptr, x, nullptr, outp, NNODE);
}